// round 9
// baseline (speedup 1.0000x reference)
#include <cuda_runtime.h>
#include <cstdint>

// Problem shape (fixed by the reference setup_inputs)
#define B_SZ   4
#define N_PTS  8192
#define M_PTS  8192

// Chamfer compute tiling (R5 config: best measured)
#define BLOCK  128                 // threads per block (4 warps)
#define OWN    8                   // owner pred points per thread
#define TI     (BLOCK * OWN)       // 1024 pred points per block
#define TILE   256                 // target points per block (one shared tile)
#define TILE2  (TILE / 2)          // packed j-pairs
#define IC     (N_PTS / TI)        // 8  i-chunks
#define JC     (M_PTS / TILE)      // 32 j-chunks
#define NPTS_T (B_SZ * N_PTS)      // 32768 (== B_SZ * M_PTS)

#define FINF __int_as_float(0x7f800000)

typedef unsigned long long ull;

// Non-atomic partial-min arrays: every slot written exactly once by one block.
__device__ float gPartX[JC][NPTS_T];   // [jc][b*N+i]: min over j-slice of 0.5*d^2
__device__ float gPartY[IC][NPTS_T];   // [ic][b*M+j]: min over i-slice of 0.5*d^2
__device__ float gSumX;
__device__ float gSumY;
__device__ int   gCount;

// ---- packed f32x2 helpers ----
__device__ __forceinline__ ull pack2(float lo, float hi) {
    ull r;
    asm("mov.b64 %0, {%1,%2};" : "=l"(r) : "f"(lo), "f"(hi));
    return r;
}
__device__ __forceinline__ ull fma2(ull a, ull b, ull c) {
    ull d;
    asm("fma.rn.f32x2 %0, %1, %2, %3;" : "=l"(d) : "l"(a), "l"(b), "l"(c));
    return d;
}
__device__ __forceinline__ ull add2(ull a, ull b) {
    ull d;
    asm("add.rn.f32x2 %0, %1, %2;" : "=l"(d) : "l"(a), "l"(b));
    return d;
}
__device__ __forceinline__ void unpack2(ull v, float& lo, float& hi) {
    asm("mov.b64 {%0,%1}, %2;" : "=f"(lo), "=f"(hi) : "l"(v));
}

// Each unique pair (i,j) computed exactly ONCE as v = 0.5*d^2(i,j):
//   v = (0.5|t_j|^2 + 0.5|p_i|^2) - p_i . t_j    [1 add2 + 3 fma2, packed over 2 j's]
// Row mins: register accumulators -> gPartX plain store.
// Col mins: per-warp shared arrays, lane-rotated jp => lane-exclusive RMW -> gPartY.
// De-stall: pairwise col trees (depth 4), LDS.128 tile loads, incremental jp.
__global__ __launch_bounds__(BLOCK, 7) void chamfer_kernel(
    const float* __restrict__ pred, const float* __restrict__ target)
{
    // Interleaved pair-packed tiles: sT0[jp]={x2,y2}, sT1[jp]={z2,w2}.
    __shared__ ulonglong2 sT0[TILE2], sT1[TILE2];
    __shared__ ull sCol[BLOCK / 32][TILE2];   // per-warp packed column mins

    const int b = blockIdx.z;
    const float* __restrict__ predB = pred   + (size_t)b * N_PTS * 3;
    const float* __restrict__ targB = target + (size_t)b * M_PTS * 3;

    const int ic = blockIdx.x;
    const int jc = blockIdx.y;
    const int Ibase = ic * TI;
    const int Jbase = jc * TILE;
    const int t = threadIdx.x;
    const int lane = t & 31;
    const int w = t >> 5;

    // init per-warp colmins to +inf
    ull inf2 = pack2(FINF, FINF);
#pragma unroll
    for (int k = t; k < (BLOCK / 32) * TILE2; k += BLOCK)
        ((ull*)sCol)[k] = inf2;

    // load target tile: pair k = {j=2k, j=2k+1}; float view of sT0[k] is
    // [x_{2k}, x_{2k+1}, y_{2k}, y_{2k+1}], sT1[k] is [z.., w..]
    for (int k = t; k < TILE; k += BLOCK) {
        int j = Jbase + k;
        int kp = k >> 1, h = k & 1;
        float x = targB[3 * j + 0], y = targB[3 * j + 1], z = targB[3 * j + 2];
        float* f0 = (float*)&sT0[kp];
        float* f1 = (float*)&sT1[kp];
        f0[0 + h] = x;
        f0[2 + h] = y;
        f1[0 + h] = z;
        f1[2 + h] = 0.5f * (x * x + y * y + z * z);
    }

    // owner pred points: negated coords + half-norm, duplicated into f32x2 pairs
    ull ax[OWN], ay[OWN], az[OWN], hp[OWN];
    float rm[OWN];
#pragma unroll
    for (int p = 0; p < OWN; p++) {
        int i = Ibase + t + p * BLOCK;
        float x = predB[3 * i + 0], y = predB[3 * i + 1], z = predB[3 * i + 2];
        float h = 0.5f * (x * x + y * y + z * z);
        ax[p] = pack2(-x, -x); ay[p] = pack2(-y, -y); az[p] = pack2(-z, -z);
        hp[p] = pack2(h, h);
        rm[p] = FINF;
    }

    __syncthreads();

    ull* scol = sCol[w];

    int jp = lane;   // lane-rotated, incremental (no add+and per step)
    for (int s = 0; s < TILE2; s++) {
        ulonglong2 t0 = sT0[jp];   // LDS.128: {x2, y2}
        ulonglong2 t1 = sT1[jp];   // LDS.128: {z2, w2}
        const ull tx = t0.x, ty = t0.y, tz = t1.x, tw = t1.y;
        float c0 = FINF, c1 = FINF;
#pragma unroll
        for (int p = 0; p < OWN; p += 2) {
            // owner p
            ull va = fma2(az[p], tz, add2(tw, hp[p]));
            va = fma2(ay[p], ty, va);
            va = fma2(ax[p], tx, va);
            // owner p+1
            ull vb = fma2(az[p + 1], tz, add2(tw, hp[p + 1]));
            vb = fma2(ay[p + 1], ty, vb);
            vb = fma2(ax[p + 1], tx, vb);
            float a0, a1, b0, b1;
            unpack2(va, a0, a1);
            unpack2(vb, b0, b1);
            rm[p]     = fminf(rm[p],     fminf(a0, a1));   // row mins
            rm[p + 1] = fminf(rm[p + 1], fminf(b0, b1));
            c0 = fminf(c0, fminf(a0, b0));                 // col partials (pair tree)
            c1 = fminf(c1, fminf(a1, b1));
        }
        // fold into per-warp column min (lane-exclusive jp, no race)
        ull cc = scol[jp];
        float o0, o1;
        unpack2(cc, o0, o1);
        scol[jp] = pack2(fminf(o0, c0), fminf(o1, c1));

        jp = (jp + 1) & (TILE2 - 1);
    }

    // row partial mins -> dedicated slice (plain store, no atomics)
    float* __restrict__ px = &gPartX[jc][b * N_PTS];
#pragma unroll
    for (int p = 0; p < OWN; p++)
        px[Ibase + t + p * BLOCK] = rm[p];

    __syncthreads();

    // column mins: combine 4 warps' arrays, one jp per thread (BLOCK == TILE2)
    {
        int q = t;
        float m0 = FINF, m1 = FINF;
#pragma unroll
        for (int w2 = 0; w2 < BLOCK / 32; w2++) {
            float a, bb;
            unpack2(sCol[w2][q], a, bb);
            m0 = fminf(m0, a);
            m1 = fminf(m1, bb);
        }
        float* __restrict__ py = &gPartY[ic][b * M_PTS + Jbase];
        py[2 * q + 0] = m0;
        py[2 * q + 1] = m1;
    }
}

// min over partial slices, global sum, (last block) finalize
__global__ __launch_bounds__(256) void reduce_fin_kernel(
    const float* __restrict__ bpp, const float* __restrict__ lamda,
    float* __restrict__ out)
{
    __shared__ float sx[256 / 32];
    __shared__ float sy[256 / 32];

    const int i = blockIdx.x * blockDim.x + threadIdx.x;   // covers B*N == B*M

    float mx = FINF;
#pragma unroll
    for (int jc = 0; jc < JC; jc++)
        mx = fminf(mx, gPartX[jc][i]);
    float my = FINF;
#pragma unroll
    for (int ic = 0; ic < IC; ic++)
        my = fminf(my, gPartY[ic][i]);

    float vx = 2.0f * mx;   // d^2 = 2 * (0.5 d^2)
    float vy = 2.0f * my;

#pragma unroll
    for (int off = 16; off > 0; off >>= 1) {
        vx += __shfl_down_sync(0xffffffffu, vx, off);
        vy += __shfl_down_sync(0xffffffffu, vy, off);
    }
    int lane = threadIdx.x & 31;
    int warp = threadIdx.x >> 5;
    if (lane == 0) { sx[warp] = vx; sy[warp] = vy; }
    __syncthreads();
    if (warp == 0) {
        vx = (lane < (256 >> 5)) ? sx[lane] : 0.0f;
        vy = (lane < (256 >> 5)) ? sy[lane] : 0.0f;
#pragma unroll
        for (int off = 4; off > 0; off >>= 1) {
            vx += __shfl_down_sync(0xffffffffu, vx, off);
            vy += __shfl_down_sync(0xffffffffu, vy, off);
        }
        if (lane == 0) {
            atomicAdd(&gSumX, vx);
            atomicAdd(&gSumY, vy);
            __threadfence();
            int ticket = atomicAdd(&gCount, 1);
            if (ticket == (int)gridDim.x - 1) {
                float sX = atomicAdd(&gSumX, 0.0f);   // all prior adds visible
                float sY = atomicAdd(&gSumY, 0.0f);
                float dist = sX * (1.0f / (B_SZ * N_PTS)) + sY * (1.0f / (B_SZ * M_PTS));
                out[0] = dist + lamda[0] * bpp[0];
                // reset for the next graph replay
                gSumX = 0.0f;
                gSumY = 0.0f;
                __threadfence();
                gCount = 0;
            }
        }
    }
}

extern "C" void kernel_launch(void* const* d_in, const int* in_sizes, int n_in,
                              void* d_out, int out_size)
{
    const float* pred   = (const float*)d_in[0];
    const float* target = (const float*)d_in[1];
    const float* bpp    = (const float*)d_in[2];
    const float* lamda  = (const float*)d_in[3];
    float* out = (float*)d_out;

    // 1) single-pass chamfer: each pair once as 0.5*d^2; partial mins to
    //    dedicated slices (no init kernel, no global atomics)
    dim3 grid(IC, JC, B_SZ);   // (8, 32, 4) = 1024 blocks
    chamfer_kernel<<<grid, BLOCK>>>(pred, target);

    // 2) slice-min + global sum + fused finalize (last-block ticket, self-reset)
    reduce_fin_kernel<<<NPTS_T / 256, 256>>>(bpp, lamda, out);
}